// round 10
// baseline (speedup 1.0000x reference)
#include <cuda_runtime.h>
#include <math.h>
#include <float.h>
#include <stdint.h>

#define NXY     36864      // 192*192 pixels
#define ETL     16
#define NDICT   4000
#define NSLOT   8          // SE (kept) columns; data-driven, padded with -1
#define REC_F   20         // floats per record (80 bytes, 2 atoms)
#define NQ      8          // dictionary slices
#define NREC    250        // records per slice (500 atoms)
#define ATOMS_S (2 * NREC)
#define PX      4          // pixels per thread
#define TPB     256
#define GRPPX   (TPB * PX)      // 1024 pixels per group
#define NGRP    (NXY / GRPPX)   // 36 pixel groups

// Per-slice partial results: key = monotone(score)<<32 | (65535 - atom).
// Every slot written exactly once per launch -> no zeroing, no atomic-max.
__device__ unsigned long long g_part[NQ * NXY];
// Arrival counters (one per pixel group). Zero at module load; atomicInc
// wraps back to 0 after NQ arrivals -> self-resetting across graph replays.
__device__ unsigned int g_cnt[NGRP];

// ---- packed f32x2 helpers (Blackwell FFMA2 path) ------------------------
#define FMA_F32X2(d, a, b, c) \
    asm("fma.rn.f32x2 %0, %1, %2, %3;" : "=l"(d) : "l"(a), "l"(b), "l"(c))
#define PACK_F32X2(out, lo, hi) \
    asm("mov.b64 %0, {%1, %2};" : "=l"(out) : "f"(lo), "f"(hi))
#define UNPACK_F32X2(lo, hi, in) \
    asm("mov.b64 {%0, %1}, %2;" : "=f"(lo), "=f"(hi) : "l"(in))

__device__ __forceinline__ void get_cols(const float* __restrict__ delta_ms,
                                         int* cols) {
    int j = 0;
    for (int k = 0; k < ETL; k++) {
        if (delta_ms[k] * 1e-3f < 1e-3f && j < NSLOT) cols[j++] = k;
    }
    for (; j < NSLOT; j++) cols[j] = -1;
}

// order-isomorphic uint32 for float compare
__device__ __forceinline__ unsigned int fmono(float f) {
    unsigned int u = __float_as_uint(f);
    return (u & 0x80000000u) ? ~u : (u | 0x80000000u);
}
__device__ __forceinline__ float fmono_inv(unsigned int u) {
    return (u & 0x80000000u) ? __uint_as_float(u ^ 0x80000000u)
                             : __uint_as_float(~u);
}

// One record = 2 atoms: 8 x (w_even, w_odd) + (bias_even, bias_odd)
struct Rec {
    ulonglong2 q0, q1, q2, q3;
    uint64_t b;
};

__device__ __forceinline__ void load_rec(Rec& r, const char* p) {
    const ulonglong2* a = (const ulonglong2*)p;
    r.q0 = a[0]; r.q1 = a[1]; r.q2 = a[2]; r.q3 = a[3];
    r.b  = *(const unsigned long long*)(p + 64);
}

// (score_even, score_odd) for one pixel; bit-deterministic FMA chain order.
__device__ __forceinline__ void rec_score(const Rec& r, const uint64_t* sp,
                                          float& lo, float& hi) {
    uint64_t acc = r.b;
    FMA_F32X2(acc, r.q0.x, sp[0], acc);
    FMA_F32X2(acc, r.q0.y, sp[1], acc);
    FMA_F32X2(acc, r.q1.x, sp[2], acc);
    FMA_F32X2(acc, r.q1.y, sp[3], acc);
    FMA_F32X2(acc, r.q2.x, sp[4], acc);
    FMA_F32X2(acc, r.q2.y, sp[5], acc);
    FMA_F32X2(acc, r.q3.x, sp[6], acc);
    FMA_F32X2(acc, r.q3.y, sp[7], acc);
    UNPACK_F32X2(lo, hi, acc);
}

// ---------------------------------------------------------------------------
// Single fused kernel. grid = 36 pixel-groups x 8 dict-slices = 288 CTAs,
// 2 CTAs/SM (20 KB static SMEM, 4 warps/SMSP). Each CTA builds its slice,
// scans it software-pipelined (record double buffer) for 1024 pixels
// (4/thread), writes partial keys; the LAST CTA of each group merges.
// ---------------------------------------------------------------------------
__global__ void __launch_bounds__(TPB, 2) fused_kernel(
    const float* __restrict__ sig,       // [NXY, ETL]
    const float* __restrict__ db_mag,    // [NDICT, ETL]
    const float* __restrict__ t2s,       // [NDICT]
    const float* __restrict__ b1s,       // [NDICT]
    const float* __restrict__ delta_ms,  // [ETL]
    float* __restrict__ out)             // [3*NXY]: t2 | b1 | min_dist
{
    __shared__ __align__(16) float sdict[NREC * REC_F];   // 20 KB
    __shared__ int s_last;

    const int group = blockIdx.x >> 3;   // 0..35
    const int q     = blockIdx.x & 7;    // dict slice

    int cols[NSLOT];
    get_cols(delta_ms, cols);

    // ---- Build this slice's packed records (normalization == reference) ----
    for (int a = threadIdx.x; a < ATOMS_S; a += TPB) {
        int ga = q * ATOMS_S + a;        // global atom index
        float v[NSLOT];
        float n2 = 0.0f;
#pragma unroll
        for (int j = 0; j < NSLOT; j++) {
            int c = cols[j];
            float x = (c >= 0) ? db_mag[ga * ETL + c] : 0.0f;
            v[j] = x;
            n2 = fmaf(x, x, n2);
        }
        float inv = 0.0f;
        if (n2 > 0.0f) {
            float r = 1.0f / sqrtf(n2);
            if (isfinite(r)) inv = r;
        }
        float* rec = sdict + (a >> 1) * REC_F;
        int par = a & 1;
        float d2 = 0.0f;
#pragma unroll
        for (int j = 0; j < NSLOT; j++) {
            float s = v[j] * inv;
            rec[2 * j + par] = 2.0f * s;     // w = 2 * normalized value
            d2 = fmaf(s, s, d2);
        }
        rec[16 + par] = -d2;                  // bias
    }

    // ---- Load + normalize this thread's 4 pixels (nan_to_num semantics) ----
    int n[PX];
    float s2px[PX];
    uint64_t sp[PX][NSLOT];
#pragma unroll
    for (int u = 0; u < PX; u++) {
        n[u] = group * GRPPX + u * TPB + threadIdx.x;
        float m[NSLOT];
        float nm2 = 0.0f;
#pragma unroll
        for (int j = 0; j < NSLOT; j++) {
            int c = cols[j];
            float v = (c >= 0) ? sig[n[u] * ETL + c] : 0.0f;
            m[j] = v;
            nm2 = fmaf(v, v, nm2);
        }
        float inv = 0.0f;
        if (nm2 > 0.0f) {
            float r = 1.0f / sqrtf(nm2);
            if (isfinite(r)) inv = r;
        }
        float acc = 0.0f;
#pragma unroll
        for (int j = 0; j < NSLOT; j++) {
            float s = m[j] * inv;
            acc = fmaf(s, s, acc);
            PACK_F32X2(sp[u][j], s, s);
        }
        s2px[u] = acc;
    }

    __syncthreads();

    // ---- Scan: 250 records, software-pipelined A/B double buffer ----
    float best[PX];
    int bit[PX];
#pragma unroll
    for (int u = 0; u < PX; u++) { best[u] = -FLT_MAX; bit[u] = 0; }

    const char* base = (const char*)sdict;
    Rec ra, rb;
    load_rec(ra, base);

#pragma unroll 1
    for (int i = 0; i < NREC; i += 2) {
        // prefetch record i+1 while scoring record i
        load_rec(rb, base + (size_t)(i + 1) * 80);
#pragma unroll
        for (int u = 0; u < PX; u++) {
            float lo, hi;
            rec_score(ra, sp[u], lo, hi);
            float m = fmaxf(lo, hi);
            if (m > best[u]) { best[u] = m; bit[u] = i; }
        }
        // prefetch record i+2 while scoring record i+1 (guarded tail)
        if (i + 2 < NREC) load_rec(ra, base + (size_t)(i + 2) * 80);
#pragma unroll
        for (int u = 0; u < PX; u++) {
            float lo, hi;
            rec_score(rb, sp[u], lo, hi);
            float m = fmaxf(lo, hi);
            if (m > best[u]) { best[u] = m; bit[u] = i + 1; }
        }
    }

    // ---- Deterministic winner recompute -> write partial key ----
    unsigned long long mykey[PX];
#pragma unroll
    for (int u = 0; u < PX; u++) {
        Rec r;
        load_rec(r, base + (size_t)bit[u] * 80);
        float lo, hi;
        rec_score(r, sp[u], lo, hi);
        int j = (lo == best[u]) ? 0 : 1;   // even lane first: lower atom wins tie
        int atom = q * ATOMS_S + 2 * bit[u] + j;
        mykey[u] = ((unsigned long long)fmono(best[u]) << 32)
                 | (unsigned long long)(65535 - atom);
        g_part[q * NXY + n[u]] = mykey[u];
    }

    // ---- Arrival: last CTA of this pixel group merges ----
    __threadfence();          // publish partial keys (release)
    __syncthreads();          // all warps' stores + fences done
    if (threadIdx.x == 0) {
        unsigned int old = atomicInc(&g_cnt[group], NQ - 1);  // wraps to 0
        s_last = (old == NQ - 1);
    }
    __syncthreads();
    if (!s_last) return;

    __threadfence();          // acquire: see all slices' partial keys
#pragma unroll
    for (int u = 0; u < PX; u++) {
        unsigned long long key = mykey[u];
#pragma unroll
        for (int qq = 0; qq < NQ; qq++) {
            unsigned long long k2 = g_part[qq * NXY + n[u]];
            if (k2 > key) key = k2;   // ties: lower atom already wins in key
        }
        int atom = 65535 - (int)(key & 0xFFFFULL);
        float score = fmono_inv((unsigned int)(key >> 32));
        float dist2 = fmaxf(s2px[u] - score, 0.0f);
        out[n[u]]           = t2s[atom];
        out[NXY + n[u]]     = b1s[atom];
        out[2 * NXY + n[u]] = sqrtf(dist2);
    }
}

// ---------------------------------------------------------------------------
extern "C" void kernel_launch(void* const* d_in, const int* in_sizes, int n_in,
                              void* d_out, int out_size) {
    const float* slice_signal = (const float*)d_in[0];  // [192,192,16]
    const float* db_mag       = (const float*)d_in[1];  // [4000,16]
    const float* db_t2s_s     = (const float*)d_in[2];  // [4000]
    const float* db_b1s       = (const float*)d_in[3];  // [4000]
    const float* delta_ms     = (const float*)d_in[4];  // [16]
    float* out = (float*)d_out;

    fused_kernel<<<NGRP * NQ, TPB>>>(slice_signal, db_mag, db_t2s_s,
                                     db_b1s, delta_ms, out);
}

// round 11
// speedup vs baseline: 1.6546x; 1.6546x over previous
#include <cuda_runtime.h>
#include <math.h>
#include <float.h>
#include <stdint.h>

#define NXY     36864      // 192*192 pixels
#define ETL     16
#define NDICT   4000
#define NSLOT   8          // SE (kept) columns; data-driven, padded with -1
#define REC_F   20         // floats per record (80 bytes, 2 atoms)
#define NQ      8          // dictionary slices
#define NREC    250        // records per slice (500 atoms)
#define ATOMS_S (2 * NREC)
#define PX      4          // pixels per thread
#define TPB     256
#define GRPPX   (TPB * PX)      // 1024 pixels per group
#define NGRP    (NXY / GRPPX)   // 36 pixel groups

// Per-slice partial results: key = monotone(score)<<32 | (65535 - atom).
// Every slot written exactly once per launch -> no zeroing, no atomic-max.
__device__ unsigned long long g_part[NQ * NXY];
// Arrival counters (one per pixel group). Zero at module load; atomicInc
// wraps back to 0 after NQ arrivals -> self-resetting across graph replays.
__device__ unsigned int g_cnt[NGRP];

// ---- packed f32x2 helpers (Blackwell FFMA2 path) ------------------------
#define FMA_F32X2(d, a, b, c) \
    asm("fma.rn.f32x2 %0, %1, %2, %3;" : "=l"(d) : "l"(a), "l"(b), "l"(c))
#define PACK_F32X2(out, lo, hi) \
    asm("mov.b64 %0, {%1, %2};" : "=l"(out) : "f"(lo), "f"(hi))
#define UNPACK_F32X2(lo, hi, in) \
    asm("mov.b64 {%0, %1}, %2;" : "=f"(lo), "=f"(hi) : "l"(in))

__device__ __forceinline__ void get_cols(const float* __restrict__ delta_ms,
                                         int* cols) {
    int j = 0;
    for (int k = 0; k < ETL; k++) {
        if (delta_ms[k] * 1e-3f < 1e-3f && j < NSLOT) cols[j++] = k;
    }
    for (; j < NSLOT; j++) cols[j] = -1;
}

// order-isomorphic uint32 for float compare
__device__ __forceinline__ unsigned int fmono(float f) {
    unsigned int u = __float_as_uint(f);
    return (u & 0x80000000u) ? ~u : (u | 0x80000000u);
}
__device__ __forceinline__ float fmono_inv(unsigned int u) {
    return (u & 0x80000000u) ? __uint_as_float(u ^ 0x80000000u)
                             : __uint_as_float(~u);
}

// (score_even, score_odd) from register-resident record words;
// bit-deterministic FMA chain order (identical everywhere).
__device__ __forceinline__ void score2(
    ulonglong2 q0, ulonglong2 q1, ulonglong2 q2, ulonglong2 q3, uint64_t b,
    const uint64_t* sp, float& lo, float& hi)
{
    uint64_t acc = b;
    FMA_F32X2(acc, q0.x, sp[0], acc);
    FMA_F32X2(acc, q0.y, sp[1], acc);
    FMA_F32X2(acc, q1.x, sp[2], acc);
    FMA_F32X2(acc, q1.y, sp[3], acc);
    FMA_F32X2(acc, q2.x, sp[4], acc);
    FMA_F32X2(acc, q2.y, sp[5], acc);
    FMA_F32X2(acc, q3.x, sp[6], acc);
    FMA_F32X2(acc, q3.y, sp[7], acc);
    UNPACK_F32X2(lo, hi, acc);
}

// load one 80-B record into 5 raw variables (4x LDS.128 + LDS.64)
#define LOAD_REC(Q0, Q1, Q2, Q3, B, byteoff) do {                           \
    const ulonglong2* _p = (const ulonglong2*)(base + (byteoff));           \
    (Q0) = _p[0]; (Q1) = _p[1]; (Q2) = _p[2]; (Q3) = _p[3];                 \
    (B)  = *(const unsigned long long*)(base + (byteoff) + 64);             \
} while (0)

// score all PX pixels against one register-resident record
#define SCORE_REC(Q0, Q1, Q2, Q3, B, recidx) do {                           \
    _Pragma("unroll")                                                       \
    for (int _u = 0; _u < PX; _u++) {                                       \
        float _lo, _hi;                                                     \
        score2((Q0), (Q1), (Q2), (Q3), (B), sp[_u], _lo, _hi);              \
        float _m = fmaxf(_lo, _hi);                                         \
        if (_m > best[_u]) { best[_u] = _m; bit[_u] = (recidx); }           \
    }                                                                       \
} while (0)

// ---------------------------------------------------------------------------
// Single fused kernel. grid = 36 pixel-groups x 8 dict-slices = 288 CTAs,
// 2 CTAs/SM (20 KB static SMEM, 4 warps/SMSP). Copy-free software pipeline:
// raw A/B register buffers, loads of record i+1 overlap scoring of record i.
// ---------------------------------------------------------------------------
__global__ void __launch_bounds__(TPB, 2) fused_kernel(
    const float* __restrict__ sig,       // [NXY, ETL]
    const float* __restrict__ db_mag,    // [NDICT, ETL]
    const float* __restrict__ t2s,       // [NDICT]
    const float* __restrict__ b1s,       // [NDICT]
    const float* __restrict__ delta_ms,  // [ETL]
    float* __restrict__ out)             // [3*NXY]: t2 | b1 | min_dist
{
    __shared__ __align__(16) float sdict[NREC * REC_F];   // 20 KB
    __shared__ int s_last;

    const int group = blockIdx.x >> 3;   // 0..35
    const int q     = blockIdx.x & 7;    // dict slice

    int cols[NSLOT];
    get_cols(delta_ms, cols);

    // ---- Build this slice's packed records (normalization == reference) ----
    for (int a = threadIdx.x; a < ATOMS_S; a += TPB) {
        int ga = q * ATOMS_S + a;        // global atom index
        float v[NSLOT];
        float n2 = 0.0f;
#pragma unroll
        for (int j = 0; j < NSLOT; j++) {
            int c = cols[j];
            float x = (c >= 0) ? db_mag[ga * ETL + c] : 0.0f;
            v[j] = x;
            n2 = fmaf(x, x, n2);
        }
        float inv = 0.0f;
        if (n2 > 0.0f) {
            float r = 1.0f / sqrtf(n2);
            if (isfinite(r)) inv = r;
        }
        float* rec = sdict + (a >> 1) * REC_F;
        int par = a & 1;
        float d2 = 0.0f;
#pragma unroll
        for (int j = 0; j < NSLOT; j++) {
            float s = v[j] * inv;
            rec[2 * j + par] = 2.0f * s;     // w = 2 * normalized value
            d2 = fmaf(s, s, d2);
        }
        rec[16 + par] = -d2;                  // bias
    }

    // ---- Load + normalize this thread's 4 pixels (nan_to_num semantics) ----
    int n[PX];
    float s2px[PX];
    uint64_t sp[PX][NSLOT];
#pragma unroll
    for (int u = 0; u < PX; u++) {
        n[u] = group * GRPPX + u * TPB + threadIdx.x;
        float m[NSLOT];
        float nm2 = 0.0f;
#pragma unroll
        for (int j = 0; j < NSLOT; j++) {
            int c = cols[j];
            float v = (c >= 0) ? sig[n[u] * ETL + c] : 0.0f;
            m[j] = v;
            nm2 = fmaf(v, v, nm2);
        }
        float inv = 0.0f;
        if (nm2 > 0.0f) {
            float r = 1.0f / sqrtf(nm2);
            if (isfinite(r)) inv = r;
        }
        float acc = 0.0f;
#pragma unroll
        for (int j = 0; j < NSLOT; j++) {
            float s = m[j] * inv;
            acc = fmaf(s, s, acc);
            PACK_F32X2(sp[u][j], s, s);
        }
        s2px[u] = acc;
    }

    __syncthreads();

    // ---- Scan: copy-free software-pipelined double buffer ----
    float best[PX];
    int bit[PX];
#pragma unroll
    for (int u = 0; u < PX; u++) { best[u] = -FLT_MAX; bit[u] = 0; }

    const char* base = (const char*)sdict;
    ulonglong2 a0, a1, a2, a3;  uint64_t ab;   // buffer A
    ulonglong2 b0, b1q, b2, b3; uint64_t bb;   // buffer B

    LOAD_REC(a0, a1, a2, a3, ab, 0);           // prologue: rec 0 -> A

#pragma unroll 1
    for (int i = 0; i < NREC - 2; i += 2) {    // i = 0,2,...,246
        int off = i * 80;
        LOAD_REC(b0, b1q, b2, b3, bb, off + 80);    // rec i+1 -> B
        SCORE_REC(a0, a1, a2, a3, ab, i);            // score rec i
        LOAD_REC(a0, a1, a2, a3, ab, off + 160);    // rec i+2 -> A
        SCORE_REC(b0, b1q, b2, b3, bb, i + 1);       // score rec i+1
    }
    // epilogue: A holds rec 248
    LOAD_REC(b0, b1q, b2, b3, bb, (NREC - 1) * 80);  // rec 249 -> B
    SCORE_REC(a0, a1, a2, a3, ab, NREC - 2);
    SCORE_REC(b0, b1q, b2, b3, bb, NREC - 1);

    // ---- Deterministic winner recompute -> write partial key ----
    unsigned long long mykey[PX];
#pragma unroll
    for (int u = 0; u < PX; u++) {
        LOAD_REC(a0, a1, a2, a3, ab, bit[u] * 80);
        float lo, hi;
        score2(a0, a1, a2, a3, ab, sp[u], lo, hi);
        int j = (lo == best[u]) ? 0 : 1;   // even lane first: lower atom wins tie
        int atom = q * ATOMS_S + 2 * bit[u] + j;
        mykey[u] = ((unsigned long long)fmono(best[u]) << 32)
                 | (unsigned long long)(65535 - atom);
        g_part[q * NXY + n[u]] = mykey[u];
    }

    // ---- Arrival: last CTA of this pixel group merges ----
    __threadfence();          // publish partial keys (release)
    __syncthreads();          // all warps' stores + fences done
    if (threadIdx.x == 0) {
        unsigned int old = atomicInc(&g_cnt[group], NQ - 1);  // wraps to 0
        s_last = (old == NQ - 1);
    }
    __syncthreads();
    if (!s_last) return;

    __threadfence();          // acquire: see all slices' partial keys
#pragma unroll
    for (int u = 0; u < PX; u++) {
        unsigned long long key = mykey[u];
#pragma unroll
        for (int qq = 0; qq < NQ; qq++) {
            unsigned long long k2 = g_part[qq * NXY + n[u]];
            if (k2 > key) key = k2;   // ties: lower atom already wins in key
        }
        int atom = 65535 - (int)(key & 0xFFFFULL);
        float score = fmono_inv((unsigned int)(key >> 32));
        float dist2 = fmaxf(s2px[u] - score, 0.0f);
        out[n[u]]           = t2s[atom];
        out[NXY + n[u]]     = b1s[atom];
        out[2 * NXY + n[u]] = sqrtf(dist2);
    }
}

// ---------------------------------------------------------------------------
extern "C" void kernel_launch(void* const* d_in, const int* in_sizes, int n_in,
                              void* d_out, int out_size) {
    const float* slice_signal = (const float*)d_in[0];  // [192,192,16]
    const float* db_mag       = (const float*)d_in[1];  // [4000,16]
    const float* db_t2s_s     = (const float*)d_in[2];  // [4000]
    const float* db_b1s       = (const float*)d_in[3];  // [4000]
    const float* delta_ms     = (const float*)d_in[4];  // [16]
    float* out = (float*)d_out;

    fused_kernel<<<NGRP * NQ, TPB>>>(slice_signal, db_mag, db_t2s_s,
                                     db_b1s, delta_ms, out);
}